// round 12
// baseline (speedup 1.0000x reference)
#include <cuda_runtime.h>
#include <cuda_fp16.h>
#include <cstdint>

#define N_USERS 200000
#define N_EDGES 3200000
#define DIM 64
#define DV8 8                        // 8 chunks of 8 halves (uint4) per row
#define ROWS_V8 (N_USERS * DV8)      // 1,600,000 uint4 per fp16 buffer
#define SCAN_B 1024
#define N_SCAN_BLOCKS ((N_USERS + SCAN_B - 1) / SCAN_B)   // 196

// ---- static scratch (allocation-free rule) --------------------------------
__device__ uint4    g_x0h[ROWS_V8];          // 25.6 MB fp16(user_emb)
__device__ uint4    g_h0h[ROWS_V8];          // 25.6 MB fp16 layer-1 out
__device__ uint4    g_h1h[ROWS_V8];          // 25.6 MB fp16 layer-2 out
__device__ uint32_t g_perm[N_EDGES];         // 12.8 MB packed (src:18 | val_q:14)
__device__ int      g_counts[N_USERS];
__device__ int      g_row_start[N_USERS];
__device__ int      g_row_fill[N_USERS];     // post-scatter == row end
__device__ int      g_block_sums[N_SCAN_BLOCKS];

// ---- helpers ---------------------------------------------------------------
__device__ __forceinline__ void half8_to_float8(uint4 u, float* f) {
    const __half2* h = reinterpret_cast<const __half2*>(&u);
    float2 t0 = __half22float2(h[0]);
    float2 t1 = __half22float2(h[1]);
    float2 t2 = __half22float2(h[2]);
    float2 t3 = __half22float2(h[3]);
    f[0] = t0.x; f[1] = t0.y; f[2] = t1.x; f[3] = t1.y;
    f[4] = t2.x; f[5] = t2.y; f[6] = t3.x; f[7] = t3.y;
}
__device__ __forceinline__ uint4 float8_to_half8(const float* f) {
    uint4 u;
    __half2* h = reinterpret_cast<__half2*>(&u);
    h[0] = __floats2half2_rn(f[0], f[1]);
    h[1] = __floats2half2_rn(f[2], f[3]);
    h[2] = __floats2half2_rn(f[4], f[5]);
    h[3] = __floats2half2_rn(f[6], f[7]);
    return u;
}

// ---------------------------------------------------------------------------
// Fused prep: zero counts AND convert user_emb -> fp16. Grid covers ROWS_V8.
__global__ void k_prep(const float4* __restrict__ emb, uint4* __restrict__ x0h,
                       int* counts) {
    int i = blockIdx.x * blockDim.x + threadIdx.x;
    if (i < N_USERS) counts[i] = 0;
    if (i < ROWS_V8) {
        float4 a = __ldg(&emb[2 * i]);
        float4 b = __ldg(&emb[2 * i + 1]);
        float f[8] = {a.x, a.y, a.z, a.w, b.x, b.y, b.z, b.w};
        x0h[i] = float8_to_half8(f);
    }
}

// histogram of dst, int4-vectorized
__global__ void k_hist(const int4* __restrict__ dst4, int* counts, int n4) {
    int i = blockIdx.x * blockDim.x + threadIdx.x;
    if (i < n4) {
        int4 d = __ldg(&dst4[i]);
        atomicAdd(&counts[d.x], 1);
        atomicAdd(&counts[d.y], 1);
        atomicAdd(&counts[d.z], 1);
        atomicAdd(&counts[d.w], 1);
    }
}

__global__ void k_block_reduce(const int* __restrict__ counts, int* block_sums, int n) {
    __shared__ int sh[SCAN_B];
    int i = blockIdx.x * SCAN_B + threadIdx.x;
    sh[threadIdx.x] = (i < n) ? counts[i] : 0;
    __syncthreads();
    #pragma unroll
    for (int off = SCAN_B / 2; off > 0; off >>= 1) {
        if (threadIdx.x < off) sh[threadIdx.x] += sh[threadIdx.x + off];
        __syncthreads();
    }
    if (threadIdx.x == 0) block_sums[blockIdx.x] = sh[0];
}

// fused scan: redundant 196-element top scan per block + local scan
__global__ void k_scan_final(const int* __restrict__ counts,
                             const int* __restrict__ block_sums,
                             int* row_start, int* row_fill, int n) {
    __shared__ int shb[SCAN_B];
    __shared__ int shc[SCAN_B];
    shb[threadIdx.x] = (threadIdx.x < N_SCAN_BLOCKS) ? block_sums[threadIdx.x] : 0;
    __syncthreads();
    #pragma unroll
    for (int off = 1; off < SCAN_B; off <<= 1) {
        int t = (threadIdx.x >= off) ? shb[threadIdx.x - off] : 0;
        __syncthreads();
        shb[threadIdx.x] += t;
        __syncthreads();
    }
    int blk_off = (blockIdx.x > 0) ? shb[blockIdx.x - 1] : 0;

    int i = blockIdx.x * SCAN_B + threadIdx.x;
    int v = (i < n) ? counts[i] : 0;
    shc[threadIdx.x] = v;
    __syncthreads();
    #pragma unroll
    for (int off = 1; off < SCAN_B; off <<= 1) {
        int t = (threadIdx.x >= off) ? shc[threadIdx.x - off] : 0;
        __syncthreads();
        shc[threadIdx.x] += t;
        __syncthreads();
    }
    if (i < n) {
        int s = blk_off + shc[threadIdx.x] - v;
        row_start[i] = s;
        row_fill[i]  = s;
    }
}

// scatter: pack (src << 14 | quantize14(val)) into dst-grouped order
__global__ void k_scatter(const float4* __restrict__ vals4,
                          const int4* __restrict__ src4,
                          const int4* __restrict__ dst4,
                          int* row_fill, uint32_t* perm, int n4) {
    int i = blockIdx.x * blockDim.x + threadIdx.x;
    if (i >= n4) return;
    int4 s = __ldg(&src4[i]);
    int4 d = __ldg(&dst4[i]);
    float4 v = __ldg(&vals4[i]);
    int p;
    p = atomicAdd(&row_fill[d.x], 1);
    perm[p] = ((uint32_t)s.x << 14) | (uint32_t)__float2int_rn(v.x * 16383.0f);
    p = atomicAdd(&row_fill[d.y], 1);
    perm[p] = ((uint32_t)s.y << 14) | (uint32_t)__float2int_rn(v.y * 16383.0f);
    p = atomicAdd(&row_fill[d.z], 1);
    perm[p] = ((uint32_t)s.z << 14) | (uint32_t)__float2int_rn(v.z * 16383.0f);
    p = atomicAdd(&row_fill[d.w], 1);
    perm[p] = ((uint32_t)s.w << 14) | (uint32_t)__float2int_rn(v.w * 16383.0f);
}

// ---------------------------------------------------------------------------
// Pull-mode SpMM over fp16, 8 lanes/row (16B gathers), fp32 accumulation,
// dual gather chains in flight.
// MODE 0/1: h_out = fp16(G@x)
// MODE 2:   acc = (emb + h0 + h1 + G@x) * 0.25   (fp32)
template <int MODE>
__global__ void __launch_bounds__(256)
k_spmm_h8(const uint4* __restrict__ x,
          const uint32_t* __restrict__ perm,
          const int* __restrict__ row_start,
          const int* __restrict__ row_end,
          uint4* __restrict__ h_out,
          float4* __restrict__ acc,
          const float4* __restrict__ emb,
          const uint4* __restrict__ h0,
          const uint4* __restrict__ h1) {
    int t = blockIdx.x * blockDim.x + threadIdx.x;
    int row = t >> 3;
    int c   = t & 7;
    if (row >= N_USERS) return;

    int j   = __ldg(&row_start[row]);
    int end = __ldg(&row_end[row]);

    float a0[8] = {0.f}, a1[8] = {0.f};
    const float QS = 1.0f / 16383.0f;

    for (; j + 2 <= end; j += 2) {
        uint32_t p0 = __ldg(&perm[j]);
        uint32_t p1 = __ldg(&perm[j + 1]);
        uint4 u0 = __ldg(&x[(p0 >> 14) * DV8 + c]);
        uint4 u1 = __ldg(&x[(p1 >> 14) * DV8 + c]);
        float v0 = (float)(p0 & 0x3FFFu) * QS;
        float v1 = (float)(p1 & 0x3FFFu) * QS;
        float f0[8], f1[8];
        half8_to_float8(u0, f0);
        half8_to_float8(u1, f1);
        #pragma unroll
        for (int k = 0; k < 8; ++k) {
            a0[k] += v0 * f0[k];
            a1[k] += v1 * f1[k];
        }
    }
    if (j < end) {
        uint32_t p = __ldg(&perm[j]);
        uint4 u = __ldg(&x[(p >> 14) * DV8 + c]);
        float v = (float)(p & 0x3FFFu) * QS;
        float f[8];
        half8_to_float8(u, f);
        #pragma unroll
        for (int k = 0; k < 8; ++k) a0[k] += v * f[k];
    }
    float a[8];
    #pragma unroll
    for (int k = 0; k < 8; ++k) a[k] = a0[k] + a1[k];

    int o8 = row * DV8 + c;
    if (MODE == 2) {
        float b0[8], b1[8];
        half8_to_float8(__ldg(&h0[o8]), b0);
        half8_to_float8(__ldg(&h1[o8]), b1);
        int o4 = 2 * o8;
        float4 e0 = __ldg(&emb[o4]);
        float4 e1 = __ldg(&emb[o4 + 1]);
        acc[o4]     = make_float4((e0.x + b0[0] + b1[0] + a[0]) * 0.25f,
                                  (e0.y + b0[1] + b1[1] + a[1]) * 0.25f,
                                  (e0.z + b0[2] + b1[2] + a[2]) * 0.25f,
                                  (e0.w + b0[3] + b1[3] + a[3]) * 0.25f);
        acc[o4 + 1] = make_float4((e1.x + b0[4] + b1[4] + a[4]) * 0.25f,
                                  (e1.y + b0[5] + b1[5] + a[5]) * 0.25f,
                                  (e1.z + b0[6] + b1[6] + a[6]) * 0.25f,
                                  (e1.w + b0[7] + b1[7] + a[7]) * 0.25f);
    } else {
        h_out[o8] = float8_to_half8(a);
    }
}

// ---------------------------------------------------------------------------
extern "C" void kernel_launch(void* const* d_in, const int* in_sizes, int n_in,
                              void* d_out, int out_size) {
    const float4* user_emb  = (const float4*)d_in[0];
    const float*  edge_vals = (const float*)d_in[1];
    const int*    edge_src  = (const int*)d_in[2];
    const int*    edge_dst  = (const int*)d_in[3];
    float4* acc = (float4*)d_out;

    uint4 *x0h, *h0h, *h1h;
    uint32_t* perm;
    int *counts, *row_start, *row_fill, *bsums;
    cudaGetSymbolAddress((void**)&x0h, g_x0h);
    cudaGetSymbolAddress((void**)&h0h, g_h0h);
    cudaGetSymbolAddress((void**)&h1h, g_h1h);
    cudaGetSymbolAddress((void**)&perm, g_perm);
    cudaGetSymbolAddress((void**)&counts, g_counts);
    cudaGetSymbolAddress((void**)&row_start, g_row_start);
    cudaGetSymbolAddress((void**)&row_fill, g_row_fill);
    cudaGetSymbolAddress((void**)&bsums, g_block_sums);

    const int EB = 256;
    const int n4 = N_EDGES / 4;
    const int e4grid = (n4 + EB - 1) / EB;
    const int pgrid  = (ROWS_V8 + EB - 1) / EB;          // covers N_USERS too
    const int sgrid  = (N_USERS * DV8 + EB - 1) / EB;    // 8 threads/row

    // ---- prep + CSR build ----
    k_prep<<<pgrid, EB>>>(user_emb, x0h, counts);
    k_hist<<<e4grid, EB>>>((const int4*)edge_dst, counts, n4);
    k_block_reduce<<<N_SCAN_BLOCKS, SCAN_B>>>(counts, bsums, N_USERS);
    k_scan_final<<<N_SCAN_BLOCKS, SCAN_B>>>(counts, bsums, row_start, row_fill, N_USERS);
    k_scatter<<<e4grid, EB>>>((const float4*)edge_vals, (const int4*)edge_src,
                              (const int4*)edge_dst, row_fill, perm, n4);

    // ---- 3 propagation layers ----
    k_spmm_h8<0><<<sgrid, EB>>>(x0h, perm, row_start, row_fill, h0h,
                                nullptr, nullptr, nullptr, nullptr);
    k_spmm_h8<1><<<sgrid, EB>>>(h0h, perm, row_start, row_fill, h1h,
                                nullptr, nullptr, nullptr, nullptr);
    k_spmm_h8<2><<<sgrid, EB>>>(h1h, perm, row_start, row_fill, nullptr,
                                acc, user_emb, h0h, h1h);
}

// round 14
// speedup vs baseline: 1.2797x; 1.2797x over previous
#include <cuda_runtime.h>
#include <cuda_fp16.h>
#include <cstdint>

#define N_USERS 200000
#define N_EDGES 3200000
#define DIM 64
#define DV4 16                       // 16 chunks of 4 halves (uint2) per row
#define ROWS_V4 (N_USERS * DV4)      // 3,200,000 uint2 per fp16 buffer
#define SCAN_B 1024
#define N_SCAN_BLOCKS ((N_USERS + SCAN_B - 1) / SCAN_B)   // 196

// ---- static scratch (allocation-free rule) --------------------------------
__device__ uint2    g_x0h[ROWS_V4];          // 25.6 MB fp16(user_emb)
__device__ uint2    g_h0h[ROWS_V4];          // 25.6 MB fp16 layer-1 out
__device__ uint2    g_h1h[ROWS_V4];          // 25.6 MB fp16 layer-2 out
__device__ uint32_t g_perm[N_EDGES];         // 12.8 MB packed (src:18 | val_q:14)
__device__ int      g_counts[N_USERS];
__device__ int      g_row_start[N_USERS];
__device__ int      g_row_fill[N_USERS];     // post-scatter == row end
__device__ int      g_block_sums[N_SCAN_BLOCKS];

// ---- fp16 helpers (4-wide) --------------------------------------------------
__device__ __forceinline__ float4 half4_to_float4(uint2 u) {
    __half2 a = *reinterpret_cast<__half2*>(&u.x);
    __half2 b = *reinterpret_cast<__half2*>(&u.y);
    float2 fa = __half22float2(a);
    float2 fb = __half22float2(b);
    return make_float4(fa.x, fa.y, fb.x, fb.y);
}
__device__ __forceinline__ uint2 float4_to_half4(float4 f) {
    __half2 a = __floats2half2_rn(f.x, f.y);
    __half2 b = __floats2half2_rn(f.z, f.w);
    uint2 u;
    u.x = *reinterpret_cast<uint32_t*>(&a);
    u.y = *reinterpret_cast<uint32_t*>(&b);
    return u;
}

// ---------------------------------------------------------------------------
// Fused prep: zero counts AND convert user_emb -> fp16. Grid covers ROWS_V4.
__global__ void k_prep(const float4* __restrict__ emb, uint2* __restrict__ x0h,
                       int* counts) {
    int i = blockIdx.x * blockDim.x + threadIdx.x;
    if (i < N_USERS) counts[i] = 0;
    if (i < ROWS_V4) x0h[i] = float4_to_half4(__ldg(&emb[i]));
}

// histogram of dst, int4-vectorized (N_EDGES % 4 == 0)
__global__ void k_hist(const int4* __restrict__ dst4, int* counts, int n4) {
    int i = blockIdx.x * blockDim.x + threadIdx.x;
    if (i < n4) {
        int4 d = __ldg(&dst4[i]);
        atomicAdd(&counts[d.x], 1);
        atomicAdd(&counts[d.y], 1);
        atomicAdd(&counts[d.z], 1);
        atomicAdd(&counts[d.w], 1);
    }
}

__global__ void k_block_reduce(const int* __restrict__ counts, int* block_sums, int n) {
    __shared__ int sh[SCAN_B];
    int i = blockIdx.x * SCAN_B + threadIdx.x;
    sh[threadIdx.x] = (i < n) ? counts[i] : 0;
    __syncthreads();
    #pragma unroll
    for (int off = SCAN_B / 2; off > 0; off >>= 1) {
        if (threadIdx.x < off) sh[threadIdx.x] += sh[threadIdx.x + off];
        __syncthreads();
    }
    if (threadIdx.x == 0) block_sums[blockIdx.x] = sh[0];
}

// fused scan: redundant 196-element top scan per block + local scan
__global__ void k_scan_final(const int* __restrict__ counts,
                             const int* __restrict__ block_sums,
                             int* row_start, int* row_fill, int n) {
    __shared__ int shb[SCAN_B];
    __shared__ int shc[SCAN_B];
    shb[threadIdx.x] = (threadIdx.x < N_SCAN_BLOCKS) ? block_sums[threadIdx.x] : 0;
    __syncthreads();
    #pragma unroll
    for (int off = 1; off < SCAN_B; off <<= 1) {
        int t = (threadIdx.x >= off) ? shb[threadIdx.x - off] : 0;
        __syncthreads();
        shb[threadIdx.x] += t;
        __syncthreads();
    }
    int blk_off = (blockIdx.x > 0) ? shb[blockIdx.x - 1] : 0;

    int i = blockIdx.x * SCAN_B + threadIdx.x;
    int v = (i < n) ? counts[i] : 0;
    shc[threadIdx.x] = v;
    __syncthreads();
    #pragma unroll
    for (int off = 1; off < SCAN_B; off <<= 1) {
        int t = (threadIdx.x >= off) ? shc[threadIdx.x - off] : 0;
        __syncthreads();
        shc[threadIdx.x] += t;
        __syncthreads();
    }
    if (i < n) {
        int s = blk_off + shc[threadIdx.x] - v;
        row_start[i] = s;
        row_fill[i]  = s;
    }
}

// scatter: pack (src << 14 | quantize14(val)) into dst-grouped order
__global__ void k_scatter(const float4* __restrict__ vals4,
                          const int4* __restrict__ src4,
                          const int4* __restrict__ dst4,
                          int* row_fill, uint32_t* perm, int n4) {
    int i = blockIdx.x * blockDim.x + threadIdx.x;
    if (i >= n4) return;
    int4 s = __ldg(&src4[i]);
    int4 d = __ldg(&dst4[i]);
    float4 v = __ldg(&vals4[i]);
    int p;
    p = atomicAdd(&row_fill[d.x], 1);
    perm[p] = ((uint32_t)s.x << 14) | (uint32_t)__float2int_rn(v.x * 16383.0f);
    p = atomicAdd(&row_fill[d.y], 1);
    perm[p] = ((uint32_t)s.y << 14) | (uint32_t)__float2int_rn(v.y * 16383.0f);
    p = atomicAdd(&row_fill[d.z], 1);
    perm[p] = ((uint32_t)s.z << 14) | (uint32_t)__float2int_rn(v.z * 16383.0f);
    p = atomicAdd(&row_fill[d.w], 1);
    perm[p] = ((uint32_t)s.w << 14) | (uint32_t)__float2int_rn(v.w * 16383.0f);
}

// ---------------------------------------------------------------------------
// Pull-mode SpMM over fp16, 16 lanes/row (8B gathers = max thread-level MLP),
// fp32 accumulation, dual gather chains in flight.
// MODE 0/1: h_out = fp16(G@x)
// MODE 2:   acc = (emb + h0 + h1 + G@x) * 0.25   (fp32)
template <int MODE>
__global__ void __launch_bounds__(256)
k_spmm_h4(const uint2* __restrict__ x,
          const uint32_t* __restrict__ perm,
          const int* __restrict__ row_start,
          const int* __restrict__ row_end,
          uint2* __restrict__ h_out,
          float4* __restrict__ acc,
          const float4* __restrict__ emb,
          const uint2* __restrict__ h0,
          const uint2* __restrict__ h1) {
    int t = blockIdx.x * blockDim.x + threadIdx.x;
    int row = t >> 4;
    int c   = t & 15;
    if (row >= N_USERS) return;

    int j   = __ldg(&row_start[row]);
    int end = __ldg(&row_end[row]);

    float4 a0 = make_float4(0.f, 0.f, 0.f, 0.f);
    float4 a1 = make_float4(0.f, 0.f, 0.f, 0.f);
    const float QS = 1.0f / 16383.0f;

    for (; j + 2 <= end; j += 2) {
        uint32_t p0 = __ldg(&perm[j]);
        uint32_t p1 = __ldg(&perm[j + 1]);
        uint2 u0 = __ldg(&x[(p0 >> 14) * DV4 + c]);
        uint2 u1 = __ldg(&x[(p1 >> 14) * DV4 + c]);
        float v0 = (float)(p0 & 0x3FFFu) * QS;
        float v1 = (float)(p1 & 0x3FFFu) * QS;
        float4 x0 = half4_to_float4(u0);
        float4 x1 = half4_to_float4(u1);
        a0.x += v0 * x0.x; a0.y += v0 * x0.y; a0.z += v0 * x0.z; a0.w += v0 * x0.w;
        a1.x += v1 * x1.x; a1.y += v1 * x1.y; a1.z += v1 * x1.z; a1.w += v1 * x1.w;
    }
    if (j < end) {
        uint32_t p = __ldg(&perm[j]);
        uint2 u = __ldg(&x[(p >> 14) * DV4 + c]);
        float v = (float)(p & 0x3FFFu) * QS;
        float4 xv = half4_to_float4(u);
        a0.x += v * xv.x; a0.y += v * xv.y; a0.z += v * xv.z; a0.w += v * xv.w;
    }
    float4 a = make_float4(a0.x + a1.x, a0.y + a1.y, a0.z + a1.z, a0.w + a1.w);

    int o = row * DV4 + c;
    if (MODE == 2) {
        float4 e  = __ldg(&emb[o]);
        float4 b0 = half4_to_float4(__ldg(&h0[o]));
        float4 b1 = half4_to_float4(__ldg(&h1[o]));
        acc[o] = make_float4((e.x + b0.x + b1.x + a.x) * 0.25f,
                             (e.y + b0.y + b1.y + a.y) * 0.25f,
                             (e.z + b0.z + b1.z + a.z) * 0.25f,
                             (e.w + b0.w + b1.w + a.w) * 0.25f);
    } else {
        h_out[o] = float4_to_half4(a);
    }
}

// ---------------------------------------------------------------------------
extern "C" void kernel_launch(void* const* d_in, const int* in_sizes, int n_in,
                              void* d_out, int out_size) {
    const float4* user_emb  = (const float4*)d_in[0];
    const float*  edge_vals = (const float*)d_in[1];
    const int*    edge_src  = (const int*)d_in[2];
    const int*    edge_dst  = (const int*)d_in[3];
    float4* acc = (float4*)d_out;

    uint2 *x0h, *h0h, *h1h;
    uint32_t* perm;
    int *counts, *row_start, *row_fill, *bsums;
    cudaGetSymbolAddress((void**)&x0h, g_x0h);
    cudaGetSymbolAddress((void**)&h0h, g_h0h);
    cudaGetSymbolAddress((void**)&h1h, g_h1h);
    cudaGetSymbolAddress((void**)&perm, g_perm);
    cudaGetSymbolAddress((void**)&counts, g_counts);
    cudaGetSymbolAddress((void**)&row_start, g_row_start);
    cudaGetSymbolAddress((void**)&row_fill, g_row_fill);
    cudaGetSymbolAddress((void**)&bsums, g_block_sums);

    const int EB = 256;
    const int n4 = N_EDGES / 4;
    const int e4grid = (n4 + EB - 1) / EB;
    const int pgrid  = (ROWS_V4 + EB - 1) / EB;          // covers N_USERS too
    const int sgrid  = (N_USERS * DV4 + EB - 1) / EB;    // 16 threads/row

    // ---- prep + CSR build ----
    k_prep<<<pgrid, EB>>>(user_emb, x0h, counts);
    k_hist<<<e4grid, EB>>>((const int4*)edge_dst, counts, n4);
    k_block_reduce<<<N_SCAN_BLOCKS, SCAN_B>>>(counts, bsums, N_USERS);
    k_scan_final<<<N_SCAN_BLOCKS, SCAN_B>>>(counts, bsums, row_start, row_fill, N_USERS);
    k_scatter<<<e4grid, EB>>>((const float4*)edge_vals, (const int4*)edge_src,
                              (const int4*)edge_dst, row_fill, perm, n4);

    // ---- 3 propagation layers ----
    k_spmm_h4<0><<<sgrid, EB>>>(x0h, perm, row_start, row_fill, h0h,
                                nullptr, nullptr, nullptr, nullptr);
    k_spmm_h4<1><<<sgrid, EB>>>(h0h, perm, row_start, row_fill, h1h,
                                nullptr, nullptr, nullptr, nullptr);
    k_spmm_h4<2><<<sgrid, EB>>>(h1h, perm, row_start, row_fill, nullptr,
                                acc, user_emb, h0h, h1h);
}